// round 1
// baseline (speedup 1.0000x reference)
#include <cuda_runtime.h>

// Problem shape (fixed by dataset)
static constexpr int Dk   = 4096;       // input dim
static constexpr int Hh   = 8;          // heads
static constexpr int Rr   = 16;         // rank
static constexpr int Kmid = Hh * Rr;    // 128
static constexpr int Oo   = 4096;       // output dim
static constexpr int NTOK = 4 * 2048;   // B*S = 8192 tokens

// Scratch (no allocation allowed -> device globals)
__device__ float g_wlow[NTOK * Kmid];   // 4 MB: score-weighted low-rank activations
__device__ float g_Bt[Kmid * Oo];       // 2 MB: Bt[k][o] = B[h][o][rr], k = h*16+rr

// ---------------------------------------------------------------------------
// Kernel 0: transpose B[h][o][rr] -> Bt[(h*16+rr)][o]  (8 MB, L2-resident)
// ---------------------------------------------------------------------------
__global__ void prep_bt(const float* __restrict__ Bsrc) {
    int idx = blockIdx.x * blockDim.x + threadIdx.x;
    if (idx >= Kmid * Oo) return;
    int k = idx >> 12;          // / 4096
    int o = idx & (Oo - 1);
    int h = k >> 4;
    int rr = k & 15;
    g_Bt[idx] = Bsrc[(h * Oo + o) * Rr + rr];
}

// ---------------------------------------------------------------------------
// Kernel 1: fused   low = x @ Acat^T ,  logits = x @ Wr^T + br ,
//           scores = H*softmax(logits)*SCALING ,  wlow = low * scores
// GEMM tile: BM=64 tokens x 136 cols (128 low + 8 router), BK=16
// 256 threads, main microkernel TM=4 x TN=8
// ---------------------------------------------------------------------------
static constexpr int BM2 = 64;
static constexpr int BK  = 16;
static constexpr int XLD = BM2 + 4;    // 68, multiple of 4 for float4 LDS
static constexpr int WLD = 136 + 4;    // 140

__global__ __launch_bounds__(256)
void fused_low_router(const float* __restrict__ x,
                      const float* __restrict__ A,
                      const float* __restrict__ Wr,
                      const float* __restrict__ br) {
    __shared__ float xs[BK][XLD];          // [k][token]
    __shared__ float ws[BK][WLD];          // [k][col]   cols 0..127 = A rows, 128..135 = Wr rows
    __shared__ float slog[BM2 * 8];
    __shared__ float ssc[BM2 * 8];

    const int tid  = threadIdx.x;
    const int tx   = tid & 15;             // col group (8 cols each)
    const int ty   = tid >> 4;             // token group (4 tokens each)
    const int tok0 = blockIdx.x * BM2;

    float acc[4][8];
#pragma unroll
    for (int i = 0; i < 4; i++)
#pragma unroll
        for (int j = 0; j < 8; j++) acc[i][j] = 0.0f;

    // router pairs: 64 tokens x 8 heads = 512 pairs, 2 per thread
    float racc0 = 0.0f, racc1 = 0.0f;
    const int id0 = tid, id1 = tid + 256;
    const int rt0 = id0 >> 3, rh0 = id0 & 7;
    const int rt1 = id1 >> 3, rh1 = id1 & 7;

    // x-tile loader mapping: 64 tokens x 4 float4 = 256 float4, one per thread
    const int lt = tid >> 2;               // token 0..63
    const int lq = tid & 3;                // quad  0..3

    for (int kk = 0; kk < Dk; kk += BK) {
        // load x tile (coalesced 64B per token row)
        {
            float4 v = *reinterpret_cast<const float4*>(
                &x[(size_t)(tok0 + lt) * Dk + kk + lq * 4]);
            xs[lq * 4 + 0][lt] = v.x;
            xs[lq * 4 + 1][lt] = v.y;
            xs[lq * 4 + 2][lt] = v.z;
            xs[lq * 4 + 3][lt] = v.w;
        }
        // load weight tile: 136 rows x 4 float4 = 544
#pragma unroll 2
        for (int i = tid; i < 136 * 4; i += 256) {
            int row = i >> 2, q = i & 3;
            const float* src = (row < 128) ? (A + (size_t)row * Dk)
                                           : (Wr + (size_t)(row - 128) * Dk);
            float4 v = *reinterpret_cast<const float4*>(&src[kk + q * 4]);
            ws[q * 4 + 0][row] = v.x;
            ws[q * 4 + 1][row] = v.y;
            ws[q * 4 + 2][row] = v.z;
            ws[q * 4 + 3][row] = v.w;
        }
        __syncthreads();

#pragma unroll
        for (int k = 0; k < BK; k++) {
            float4 a  = *reinterpret_cast<const float4*>(&xs[k][ty * 4]);
            float4 b0 = *reinterpret_cast<const float4*>(&ws[k][tx * 8]);
            float4 b1 = *reinterpret_cast<const float4*>(&ws[k][tx * 8 + 4]);
            float av[4] = {a.x, a.y, a.z, a.w};
            float bv[8] = {b0.x, b0.y, b0.z, b0.w, b1.x, b1.y, b1.z, b1.w};
#pragma unroll
            for (int i = 0; i < 4; i++)
#pragma unroll
                for (int j = 0; j < 8; j++)
                    acc[i][j] = fmaf(av[i], bv[j], acc[i][j]);
            // router dots ride along (6% extra FMA)
            racc0 = fmaf(xs[k][rt0], ws[k][128 + rh0], racc0);
            racc1 = fmaf(xs[k][rt1], ws[k][128 + rh1], racc1);
        }
        __syncthreads();
    }

    // softmax over heads, fold H * SCALING = 8 * 2 = 16 into scores
    slog[id0] = racc0;
    slog[id1] = racc1;
    __syncthreads();
    if (tid < BM2) {
        float l[8], m = -1e30f;
#pragma unroll
        for (int h = 0; h < 8; h++) {
            l[h] = slog[tid * 8 + h] + br[h];
            m = fmaxf(m, l[h]);
        }
        float s = 0.0f;
#pragma unroll
        for (int h = 0; h < 8; h++) { l[h] = __expf(l[h] - m); s += l[h]; }
        float inv = 16.0f / s;
#pragma unroll
        for (int h = 0; h < 8; h++) ssc[tid * 8 + h] = l[h] * inv;
    }
    __syncthreads();

    // scale by score (head = col/16 = tx/2, constant over this thread's 8 cols)
#pragma unroll
    for (int i = 0; i < 4; i++) {
        int t = ty * 4 + i;
        float sc = ssc[t * 8 + (tx >> 1)];
        float4 o0 = make_float4(acc[i][0] * sc, acc[i][1] * sc,
                                acc[i][2] * sc, acc[i][3] * sc);
        float4 o1 = make_float4(acc[i][4] * sc, acc[i][5] * sc,
                                acc[i][6] * sc, acc[i][7] * sc);
        float* dst = &g_wlow[(size_t)(tok0 + t) * Kmid + tx * 8];
        *reinterpret_cast<float4*>(dst)     = o0;
        *reinterpret_cast<float4*>(dst + 4) = o1;
    }
}

// ---------------------------------------------------------------------------
// Kernel 2: out = wlow[8192,128] @ Bt[128,4096]
// tile BM=128 x BN=128 x BK=16, 256 threads, 8x8 microkernel
// ---------------------------------------------------------------------------
static constexpr int BM3 = 128;
static constexpr int BN3 = 128;
static constexpr int ALD = 132;

__global__ __launch_bounds__(256)
void up_gemm(float* __restrict__ out) {
    __shared__ float as[BK][ALD];          // [k][token]
    __shared__ float bs[BK][ALD];          // [k][o]

    const int tid = threadIdx.x;
    const int tx  = tid & 15;
    const int ty  = tid >> 4;
    const int o0  = blockIdx.x * BN3;
    const int m0  = blockIdx.y * BM3;

    float acc[8][8];
#pragma unroll
    for (int i = 0; i < 8; i++)
#pragma unroll
        for (int j = 0; j < 8; j++) acc[i][j] = 0.0f;

    for (int kk = 0; kk < Kmid; kk += BK) {
#pragma unroll
        for (int p = 0; p < 2; p++) {
            int i = tid + p * 256;
            // wlow tile: 128 tokens x 4 float4
            int t = i >> 2, q = i & 3;
            float4 v = *reinterpret_cast<const float4*>(
                &g_wlow[(size_t)(m0 + t) * Kmid + kk + q * 4]);
            as[q * 4 + 0][t] = v.x;
            as[q * 4 + 1][t] = v.y;
            as[q * 4 + 2][t] = v.z;
            as[q * 4 + 3][t] = v.w;
            // Bt tile: 16 k-rows x 32 float4, row-major -> direct float4 STS
            int kb = i >> 5, ob = i & 31;
            float4 w = *reinterpret_cast<const float4*>(
                &g_Bt[(size_t)(kk + kb) * Oo + o0 + ob * 4]);
            *reinterpret_cast<float4*>(&bs[kb][ob * 4]) = w;
        }
        __syncthreads();

#pragma unroll
        for (int k = 0; k < BK; k++) {
            float4 a0 = *reinterpret_cast<const float4*>(&as[k][ty * 8]);
            float4 a1 = *reinterpret_cast<const float4*>(&as[k][ty * 8 + 4]);
            float4 b0 = *reinterpret_cast<const float4*>(&bs[k][tx * 8]);
            float4 b1 = *reinterpret_cast<const float4*>(&bs[k][tx * 8 + 4]);
            float av[8] = {a0.x, a0.y, a0.z, a0.w, a1.x, a1.y, a1.z, a1.w};
            float bv[8] = {b0.x, b0.y, b0.z, b0.w, b1.x, b1.y, b1.z, b1.w};
#pragma unroll
            for (int i = 0; i < 8; i++)
#pragma unroll
                for (int j = 0; j < 8; j++)
                    acc[i][j] = fmaf(av[i], bv[j], acc[i][j]);
        }
        __syncthreads();
    }

#pragma unroll
    for (int i = 0; i < 8; i++) {
        int row = m0 + ty * 8 + i;
        float* dst = &out[(size_t)row * Oo + o0 + tx * 8];
        *reinterpret_cast<float4*>(dst) =
            make_float4(acc[i][0], acc[i][1], acc[i][2], acc[i][3]);
        *reinterpret_cast<float4*>(dst + 4) =
            make_float4(acc[i][4], acc[i][5], acc[i][6], acc[i][7]);
    }
}

// ---------------------------------------------------------------------------
extern "C" void kernel_launch(void* const* d_in, const int* in_sizes, int n_in,
                              void* d_out, int out_size) {
    const float* x  = (const float*)d_in[0];
    const float* A  = (const float*)d_in[1];
    const float* Bm = (const float*)d_in[2];
    const float* Wr = (const float*)d_in[3];
    const float* br = (const float*)d_in[4];
    float* out = (float*)d_out;

    prep_bt<<<(Kmid * Oo + 255) / 256, 256>>>(Bm);
    fused_low_router<<<NTOK / BM2, 256>>>(x, A, Wr, br);
    up_gemm<<<dim3(Oo / BN3, NTOK / BM3), 256>>>(out);
}

// round 2
// speedup vs baseline: 3.4731x; 3.4731x over previous
#include <cuda_runtime.h>
#include <stdint.h>

static constexpr int Dk   = 4096;
static constexpr int Oo   = 4096;
static constexpr int Kmid = 128;     // H*r = 8*16
static constexpr int NTOK = 8192;    // B*S

// Scratch (device globals — no allocation allowed)
__device__ float g_wlow[NTOK * Kmid];   // 4 MB, tf32-rounded, score-weighted low-rank acts
__device__ float g_Bt[Kmid * Oo];       // 2 MB, tf32-rounded, Bt[k][o] = B[h][o][rr]

// ---------------------------------------------------------------------------
// helpers
// ---------------------------------------------------------------------------
__device__ __forceinline__ float tf32r(float x) {
    uint32_t u;
    asm("cvt.rna.tf32.f32 %0, %1;" : "=r"(u) : "f"(x));
    return __uint_as_float(u);
}
__device__ __forceinline__ float4 tf32r4(float4 v) {
    return make_float4(tf32r(v.x), tf32r(v.y), tf32r(v.z), tf32r(v.w));
}
// m16n8k8 tf32 mma, C += A*B
__device__ __forceinline__ void mma8(float* c, const uint32_t* a,
                                     uint32_t b0, uint32_t b1) {
    asm volatile(
        "mma.sync.aligned.m16n8k8.row.col.f32.tf32.tf32.f32 "
        "{%0,%1,%2,%3}, {%4,%5,%6,%7}, {%8,%9}, {%0,%1,%2,%3};\n"
        : "+f"(c[0]), "+f"(c[1]), "+f"(c[2]), "+f"(c[3])
        : "r"(a[0]), "r"(a[1]), "r"(a[2]), "r"(a[3]), "r"(b0), "r"(b1));
}

// ---------------------------------------------------------------------------
// Kernel 0: transpose B[h][o][rr] -> Bt[(h*16+rr)][o], tf32-rounded
// ---------------------------------------------------------------------------
__global__ void prep_bt(const float* __restrict__ Bsrc) {
    int idx = blockIdx.x * blockDim.x + threadIdx.x;
    if (idx >= Kmid * Oo) return;
    int k = idx >> 12;
    int o = idx & (Oo - 1);
    int h = k >> 4;
    int rr = k & 15;
    g_Bt[idx] = tf32r(Bsrc[((size_t)(h * Oo + o)) * 16 + rr]);
}

// ---------------------------------------------------------------------------
// Kernel 1: tf32 mma  low = x @ Acat^T (+ router logits as extra n-tile),
//           softmax over heads, wlow = low * (16 * softmax) stored tf32.
// BM=64 x BN=128(+8) x BK=32, 256 thr, warp tile 32x32 (2 m16 x 4 n8)
// ---------------------------------------------------------------------------
static constexpr int BK1 = 32;
static constexpr int XS  = 36;   // smem stride (floats): conflict-free frag LDS

__global__ __launch_bounds__(256)
void fused_low_router(const float* __restrict__ x,
                      const float* __restrict__ A,
                      const float* __restrict__ Wr,
                      const float* __restrict__ br) {
    __shared__ float xs[64 * XS];     // [m][k]
    __shared__ float ws[136 * XS];    // [n][k]  n<128: A rows, n>=128: Wr rows
    __shared__ float slog[64 * 8];
    __shared__ float ssc[64 * 8];

    const int tid  = threadIdx.x;
    const int lane = tid & 31, wid = tid >> 5;
    const int wm = wid & 1;          // m half   (rows wm*32)
    const int wn = wid >> 1;         // n quarter(cols wn*32)
    const int r = lane >> 2, cc = lane & 3;
    const int tok0 = blockIdx.x * 64;
    const bool do_r = (wn == 0);     // warps 0,1 also do the router n-tile

    float acc[2][4][4] = {};
    float racc[2][4]   = {};

    float4 rx[2], rwv[4], rw4;

    auto LDG = [&](int kk) {
#pragma unroll
        for (int p = 0; p < 2; p++) {
            int i = tid + p * 256, m = i >> 3, q = i & 7;
            rx[p] = *reinterpret_cast<const float4*>(
                &x[(size_t)(tok0 + m) * Dk + kk + 4 * q]);
        }
#pragma unroll
        for (int p = 0; p < 4; p++) {
            int i = tid + p * 256, row = i >> 3, q = i & 7;
            rwv[p] = *reinterpret_cast<const float4*>(
                &A[(size_t)row * Dk + kk + 4 * q]);
        }
        if (tid < 64) {
            int row = tid >> 3, q = tid & 7;
            rw4 = *reinterpret_cast<const float4*>(
                &Wr[(size_t)row * Dk + kk + 4 * q]);
        }
    };
    auto STS = [&]() {
#pragma unroll
        for (int p = 0; p < 2; p++) {
            int i = tid + p * 256, m = i >> 3, q = i & 7;
            *reinterpret_cast<float4*>(&xs[m * XS + 4 * q]) = tf32r4(rx[p]);
        }
#pragma unroll
        for (int p = 0; p < 4; p++) {
            int i = tid + p * 256, row = i >> 3, q = i & 7;
            *reinterpret_cast<float4*>(&ws[row * XS + 4 * q]) = tf32r4(rwv[p]);
        }
        if (tid < 64) {
            int row = 128 + (tid >> 3), q = tid & 7;
            *reinterpret_cast<float4*>(&ws[row * XS + 4 * q]) = tf32r4(rw4);
        }
    };

    LDG(0);
    for (int kk = 0; kk < Dk; kk += BK1) {
        __syncthreads();
        STS();
        __syncthreads();
        if (kk + BK1 < Dk) LDG(kk + BK1);   // prefetch overlaps compute

        const uint32_t* xu = reinterpret_cast<const uint32_t*>(xs);
        const uint32_t* wu = reinterpret_cast<const uint32_t*>(ws);
#pragma unroll
        for (int ks = 0; ks < 4; ks++) {
            const int k0 = ks * 8;
            uint32_t a[2][4];
#pragma unroll
            for (int mt = 0; mt < 2; mt++) {
                int base = (wm * 32 + mt * 16 + r) * XS + k0 + cc;
                a[mt][0] = xu[base];
                a[mt][1] = xu[base + 8 * XS];
                a[mt][2] = xu[base + 4];
                a[mt][3] = xu[base + 8 * XS + 4];
            }
#pragma unroll
            for (int nt = 0; nt < 4; nt++) {
                int nb = (wn * 32 + nt * 8 + r) * XS + k0 + cc;
                uint32_t b0 = wu[nb], b1 = wu[nb + 4];
                mma8(acc[0][nt], a[0], b0, b1);
                mma8(acc[1][nt], a[1], b0, b1);
            }
            if (do_r) {
                int nb = (128 + r) * XS + k0 + cc;
                uint32_t b0 = wu[nb], b1 = wu[nb + 4];
                mma8(racc[0], a[0], b0, b1);
                mma8(racc[1], a[1], b0, b1);
            }
        }
    }

    // router logits -> smem
    if (do_r) {
#pragma unroll
        for (int mt = 0; mt < 2; mt++) {
            int tr = wm * 32 + mt * 16 + r;
            slog[tr * 8 + 2 * cc]           = racc[mt][0];
            slog[tr * 8 + 2 * cc + 1]       = racc[mt][1];
            slog[(tr + 8) * 8 + 2 * cc]     = racc[mt][2];
            slog[(tr + 8) * 8 + 2 * cc + 1] = racc[mt][3];
        }
    }
    __syncthreads();
    if (tid < 64) {   // softmax over 8 heads, fold H*SCALING = 16
        float l[8], m = -1e30f;
#pragma unroll
        for (int h = 0; h < 8; h++) {
            l[h] = slog[tid * 8 + h] + br[h];
            m = fmaxf(m, l[h]);
        }
        float s = 0.0f;
#pragma unroll
        for (int h = 0; h < 8; h++) { l[h] = __expf(l[h] - m); s += l[h]; }
        float inv = 16.0f / s;
#pragma unroll
        for (int h = 0; h < 8; h++) ssc[tid * 8 + h] = l[h] * inv;
    }
    __syncthreads();

    // scale by score and store wlow (tf32-rounded for kernel 2)
#pragma unroll
    for (int mt = 0; mt < 2; mt++) {
        int tr = wm * 32 + mt * 16 + r;
#pragma unroll
        for (int nt = 0; nt < 4; nt++) {
            int colb = wn * 32 + nt * 8 + 2 * cc;
            int head = (wn * 32 + nt * 8) >> 4;
            float s0 = ssc[tr * 8 + head];
            float s1 = ssc[(tr + 8) * 8 + head];
            float2 v0 = make_float2(tf32r(acc[mt][nt][0] * s0),
                                    tf32r(acc[mt][nt][1] * s0));
            float2 v1 = make_float2(tf32r(acc[mt][nt][2] * s1),
                                    tf32r(acc[mt][nt][3] * s1));
            *reinterpret_cast<float2*>(
                &g_wlow[(size_t)(tok0 + tr) * Kmid + colb]) = v0;
            *reinterpret_cast<float2*>(
                &g_wlow[(size_t)(tok0 + tr + 8) * Kmid + colb]) = v1;
        }
    }
}

// ---------------------------------------------------------------------------
// Kernel 2: out = wlow[8192,128] @ Bt[128,4096], tf32 mma
// BM=128 x BN=128 x BK=32, 256 thr, warp tile 32x64 (2 m16 x 8 n8)
// ---------------------------------------------------------------------------
static constexpr int BS2 = 136;   // bs stride: 136 % 32 == 8 -> conflict-free B frags

__global__ __launch_bounds__(256)
void up_gemm(float* __restrict__ out) {
    __shared__ float as[128 * XS];    // [m][k]
    __shared__ float bs[32 * BS2];    // [k][o]

    const int tid  = threadIdx.x;
    const int lane = tid & 31, wid = tid >> 5;
    const int mw = wid & 3;           // rows mw*32
    const int nw = wid >> 2;          // cols nw*64
    const int r = lane >> 2, cc = lane & 3;
    const int o0 = blockIdx.x * 128, m0 = blockIdx.y * 128;

    float acc[2][8][4] = {};
    float4 ra[4], rb[4];

    auto LDG = [&](int kk) {
#pragma unroll
        for (int p = 0; p < 4; p++) {
            int i = tid + p * 256, m = i >> 3, q = i & 7;
            ra[p] = *reinterpret_cast<const float4*>(
                &g_wlow[(size_t)(m0 + m) * Kmid + kk + 4 * q]);
        }
#pragma unroll
        for (int p = 0; p < 4; p++) {
            int i = tid + p * 256, k = i >> 5, o4 = i & 31;
            rb[p] = *reinterpret_cast<const float4*>(
                &g_Bt[(size_t)(kk + k) * Oo + o0 + 4 * o4]);
        }
    };
    auto STS = [&]() {
#pragma unroll
        for (int p = 0; p < 4; p++) {
            int i = tid + p * 256, m = i >> 3, q = i & 7;
            *reinterpret_cast<float4*>(&as[m * XS + 4 * q]) = ra[p];
        }
#pragma unroll
        for (int p = 0; p < 4; p++) {
            int i = tid + p * 256, k = i >> 5, o4 = i & 31;
            *reinterpret_cast<float4*>(&bs[k * BS2 + 4 * o4]) = rb[p];
        }
    };

    LDG(0);
    for (int kk = 0; kk < Kmid; kk += 32) {
        __syncthreads();
        STS();
        __syncthreads();
        if (kk + 32 < Kmid) LDG(kk + 32);

        const uint32_t* au = reinterpret_cast<const uint32_t*>(as);
        const uint32_t* bu = reinterpret_cast<const uint32_t*>(bs);
#pragma unroll
        for (int ks = 0; ks < 4; ks++) {
            const int k0 = ks * 8;
            uint32_t a[2][4];
#pragma unroll
            for (int mt = 0; mt < 2; mt++) {
                int base = (mw * 32 + mt * 16 + r) * XS + k0 + cc;
                a[mt][0] = au[base];
                a[mt][1] = au[base + 8 * XS];
                a[mt][2] = au[base + 4];
                a[mt][3] = au[base + 8 * XS + 4];
            }
#pragma unroll
            for (int nt = 0; nt < 8; nt++) {
                int nb = (k0 + cc) * BS2 + nw * 64 + nt * 8 + r;
                uint32_t b0 = bu[nb], b1 = bu[nb + 4 * BS2];
                mma8(acc[0][nt], a[0], b0, b1);
                mma8(acc[1][nt], a[1], b0, b1);
            }
        }
    }

#pragma unroll
    for (int mt = 0; mt < 2; mt++) {
        int row = m0 + mw * 32 + mt * 16 + r;
#pragma unroll
        for (int nt = 0; nt < 8; nt++) {
            int col = o0 + nw * 64 + nt * 8 + 2 * cc;
            *reinterpret_cast<float2*>(&out[(size_t)row * Oo + col]) =
                make_float2(acc[mt][nt][0], acc[mt][nt][1]);
            *reinterpret_cast<float2*>(&out[(size_t)(row + 8) * Oo + col]) =
                make_float2(acc[mt][nt][2], acc[mt][nt][3]);
        }
    }
}

// ---------------------------------------------------------------------------
extern "C" void kernel_launch(void* const* d_in, const int* in_sizes, int n_in,
                              void* d_out, int out_size) {
    const float* x  = (const float*)d_in[0];
    const float* A  = (const float*)d_in[1];
    const float* Bm = (const float*)d_in[2];
    const float* Wr = (const float*)d_in[3];
    const float* br = (const float*)d_in[4];
    float* out = (float*)d_out;

    prep_bt<<<(Kmid * Oo + 255) / 256, 256>>>(Bm);
    fused_low_router<<<NTOK / 64, 256>>>(x, A, Wr, br);
    up_gemm<<<dim3(Oo / 128, NTOK / 128), 256>>>(out);
}